// round 6
// baseline (speedup 1.0000x reference)
#include <cuda_runtime.h>
#include <cuda_bf16.h>
#include <cstdint>

#define N_TOK 8192
#define DIM   2048
#define MID   512
#define NEXP  4

#define BM 128
#define BN 64
#define KC 64                        // int8 K elems per chunk (64 B rows)
#define A_TILE_B (128 * 64)          // 8 KB
#define B_TILE_B (64 * 64)           // 4 KB
#define OFF_AHI 0
#define OFF_ALO (A_TILE_B)
#define OFF_BHI (2 * A_TILE_B)
#define OFF_BLO (2 * A_TILE_B + B_TILE_B)
#define STAGE_B (2 * A_TILE_B + 2 * B_TILE_B)   // 24 KB
#define NSTAGE 4
#define SMEM_TOT (NSTAGE * STAGE_B)  // 96 KB

#define QMAX 16256.0f                // 127*128

// ---------------- device scratch ----------------
__device__ int g_counts[NEXP];
__device__ int g_idx[NEXP * N_TOK];
__device__ int g_is64;
__device__ float g_h[(size_t)N_TOK * MID];        // fp32 intermediate
__device__ int8_t g_x1[(size_t)N_TOK * DIM];
__device__ int8_t g_x0[(size_t)N_TOK * DIM];
__device__ int8_t g_w11[(size_t)NEXP * MID * DIM];
__device__ int8_t g_w10[(size_t)NEXP * MID * DIM];
__device__ int8_t g_w21[(size_t)NEXP * DIM * MID];
__device__ int8_t g_w20[(size_t)NEXP * DIM * MID];
__device__ int8_t g_h1[(size_t)N_TOK * MID];
__device__ int8_t g_h0[(size_t)N_TOK * MID];
__device__ float g_sx[N_TOK];
__device__ float g_sw1[NEXP * MID];
__device__ float g_sw2[NEXP * DIM];
__device__ float g_sh[N_TOK];

// ---------------- helpers ----------------
__device__ __forceinline__ uint32_t smem_u32(const void* p) {
    uint32_t a;
    asm("{ .reg .u64 t; cvta.to.shared.u64 t, %1; cvt.u32.u64 %0, t; }" : "=r"(a) : "l"(p));
    return a;
}
__device__ __forceinline__ void ldm_x4(uint32_t* r, uint32_t addr) {
    asm volatile("ldmatrix.sync.aligned.m8n8.x4.shared.b16 {%0,%1,%2,%3}, [%4];"
                 : "=r"(r[0]), "=r"(r[1]), "=r"(r[2]), "=r"(r[3]) : "r"(addr));
}
__device__ __forceinline__ void imma16832(int* c, const uint32_t* a, uint32_t b0, uint32_t b1) {
    asm volatile("mma.sync.aligned.m16n8k32.row.col.s32.s8.s8.s32 "
                 "{%0,%1,%2,%3}, {%4,%5,%6,%7}, {%8,%9}, {%0,%1,%2,%3};"
                 : "+r"(c[0]), "+r"(c[1]), "+r"(c[2]), "+r"(c[3])
                 : "r"(a[0]), "r"(a[1]), "r"(a[2]), "r"(a[3]), "r"(b0), "r"(b1));
}
#define CP_ASYNC16(dst, src) \
    asm volatile("cp.async.cg.shared.global [%0], [%1], 16;" :: "r"(dst), "l"(src))
#define CP_ASYNC16_Z(dst, src, zb) \
    asm volatile("cp.async.cg.shared.global [%0], [%1], 16, %2;" :: "r"(dst), "l"(src), "r"(zb))
#define CP_COMMIT() asm volatile("cp.async.commit_group;" ::: "memory")
#define CP_WAIT2()  asm volatile("cp.async.wait_group 2;" ::: "memory")
#define CP_WAIT0()  asm volatile("cp.async.wait_group 0;" ::: "memory")

// quantize 4 floats -> hi/lo packed bytes
__device__ __forceinline__ void q4(float4 v, float inv, uint32_t& h, uint32_t& l) {
    int i0 = __float2int_rn(v.x * inv);
    int i1 = __float2int_rn(v.y * inv);
    int i2 = __float2int_rn(v.z * inv);
    int i3 = __float2int_rn(v.w * inv);
    int a0 = __float2int_rn((float)i0 * 0.0078125f);
    int a1 = __float2int_rn((float)i1 * 0.0078125f);
    int a2 = __float2int_rn((float)i2 * 0.0078125f);
    int a3 = __float2int_rn((float)i3 * 0.0078125f);
    int b0 = i0 - (a0 << 7), b1 = i1 - (a1 << 7), b2 = i2 - (a2 << 7), b3 = i3 - (a3 << 7);
    h = (a0 & 255) | ((a1 & 255) << 8) | ((a2 & 255) << 16) | ((a3 & 255) << 24);
    l = (b0 & 255) | ((b1 & 255) << 8) | ((b2 & 255) << 16) | ((b3 & 255) << 24);
}

// ---------------- setup kernels ----------------
__global__ void detect_dtype_kernel(const int* __restrict__ dom32) {
    if (threadIdx.x == 0) {
        int odd_zero = 1;
        for (int i = 1; i < 512; i += 2)
            if (dom32[i] != 0) { odd_zero = 0; break; }
        g_is64 = odd_zero;
    }
}
__global__ void zero_counts_kernel() { if (threadIdx.x < NEXP) g_counts[threadIdx.x] = 0; }

__global__ void bucket_kernel(const void* __restrict__ dom) {
    int n = blockIdx.x * blockDim.x + threadIdx.x;
    if (n >= N_TOK) return;
    int e = g_is64 ? (int)((const long long*)dom)[n] : ((const int*)dom)[n];
    int p = atomicAdd(&g_counts[e], 1);
    g_idx[e * N_TOK + p] = n;
}

// per-row 15-bit quantization: one block per row, 128 threads
__global__ __launch_bounds__(128)
void quant_rows_kernel(const float* __restrict__ src, int8_t* __restrict__ hi,
                       int8_t* __restrict__ lo, float* __restrict__ scale, int cols) {
    const int row = blockIdx.x;
    const float* r = src + (size_t)row * cols;
    const int n4 = cols >> 2;
    float amax = 0.f;
    for (int i = threadIdx.x; i < n4; i += 128) {
        float4 v = ((const float4*)r)[i];
        amax = fmaxf(amax, fmaxf(fmaxf(fabsf(v.x), fabsf(v.y)),
                                 fmaxf(fabsf(v.z), fabsf(v.w))));
    }
#pragma unroll
    for (int o = 16; o; o >>= 1) amax = fmaxf(amax, __shfl_xor_sync(~0u, amax, o));
    __shared__ float smax[4];
    if ((threadIdx.x & 31) == 0) smax[threadIdx.x >> 5] = amax;
    __syncthreads();
    amax = fmaxf(fmaxf(smax[0], smax[1]), fmaxf(smax[2], smax[3]));
    const float s   = amax > 0.f ? amax * (1.0f / QMAX) : 1.f;
    const float inv = amax > 0.f ? QMAX / amax : 0.f;
    if (threadIdx.x == 0) scale[row] = s;
    uint32_t* hp = (uint32_t*)(hi + (size_t)row * cols);
    uint32_t* lp = (uint32_t*)(lo + (size_t)row * cols);
    for (int i = threadIdx.x; i < n4; i += 128) {
        float4 v = ((const float4*)r)[i];
        uint32_t h, l;
        q4(v, inv, h, l);
        hp[i] = h;
        lp[i] = l;
    }
}

// ---------------- grouped GEMM: 4-stage cp.async + IMMA s8 3-term ----------------
// BM=128 x BN=64; 8 warps 4(m) x 2(n); warp tile 32x32. K chunks of 64 int8.
template <int KDIM, bool IS_G1>
__global__ __launch_bounds__(256, 2)
void moe_gemm_kernel(const float* __restrict__ x,
                     const int8_t* __restrict__ A_hi,
                     const int8_t* __restrict__ A_lo,
                     const float* __restrict__ sA,
                     const int8_t* __restrict__ B_hi,
                     const int8_t* __restrict__ B_lo,
                     const float* __restrict__ sB,
                     const float* __restrict__ bias,
                     float* __restrict__ out) {
    constexpr int NCH   = KDIM / KC;
    constexpr int NCOLS = IS_G1 ? MID : DIM;

    const int tiles_per_e = N_TOK / BM;            // 64
    const int e     = blockIdx.x / tiles_per_e;
    const int mtile = blockIdx.x % tiles_per_e;
    const int ntile = blockIdx.y;

    const int cnt  = g_counts[e];
    const int row0 = mtile * BM;
    if (row0 >= cnt) return;
    const int* __restrict__ idx = g_idx + e * N_TOK;

    extern __shared__ char smem[];
    const uint32_t sbase = smem_u32(smem);

    const int tid = threadIdx.x;
    const int wid = tid >> 5;
    const int lid = tid & 31;
    const int mrow0 = (wid & 3) * 32;
    const int ncol0 = (wid >> 2) * 32;

    // ---- cp.async fill mapping: row 64B = 4 x 16B chunks ----
    const int c4 = tid & 3;
    const int8_t* ahp[2];
    uint32_t zbA[2];
    uint32_t stsA[2];
#pragma unroll
    for (int i = 0; i < 2; i++) {
        const int row = (tid >> 2) + 64 * i;
        const int grow = row0 + row;
        const bool live = (grow < cnt);
        ahp[i] = live ? A_hi + (size_t)idx[grow] * KDIM + c4 * 16 : A_hi;
        zbA[i] = live ? 16u : 0u;
        stsA[i] = (uint32_t)(row * 64 + ((c4 ^ ((row >> 1) & 3)) << 4));
    }
    const int brow = tid >> 2;
    const size_t boff = ((size_t)e * NCOLS + (size_t)ntile * BN + brow) * KDIM + c4 * 16;
    const uint32_t stsB = (uint32_t)(brow * 64 + ((c4 ^ ((brow >> 1) & 3)) << 4));
    const ptrdiff_t alo_d = A_lo - A_hi;
    const ptrdiff_t blo_d = B_lo - B_hi;

    auto issue = [&](int ch, int slot) {
        const int k0 = ch * KC;
        const uint32_t st = sbase + (uint32_t)(slot * STAGE_B);
#pragma unroll
        for (int i = 0; i < 2; i++) {
            CP_ASYNC16_Z(st + OFF_AHI + stsA[i], ahp[i] + k0, zbA[i]);
            CP_ASYNC16_Z(st + OFF_ALO + stsA[i], ahp[i] + alo_d + k0, zbA[i]);
        }
        CP_ASYNC16(st + OFF_BHI + stsB, B_hi + boff + k0);
        CP_ASYNC16(st + OFF_BLO + stsB, B_hi + boff + blo_d + k0);
        CP_COMMIT();
    };

    int acc11[2][4][4], accX[2][4][4];
#pragma unroll
    for (int mi = 0; mi < 2; mi++)
#pragma unroll
        for (int nj = 0; nj < 4; nj++)
#pragma unroll
            for (int q = 0; q < 4; q++) { acc11[mi][nj][q] = 0; accX[mi][nj][q] = 0; }

    // ---- ldmatrix per-lane addresses ----
    // lane -> local row offset (l&7) + 8*((l>>3)&1); j16 = ks*2 + (l>>4)
    const int lrow = (lid & 7) + 8 * ((lid >> 3) & 1);
    const uint32_t jhalf = (uint32_t)(lid >> 4);
    uint32_t aAddr[2], aMsk[2];
#pragma unroll
    for (int mi = 0; mi < 2; mi++) {
        const int r = mrow0 + mi * 16 + lrow;
        aAddr[mi] = (uint32_t)(r * 64);
        aMsk[mi] = (uint32_t)((r >> 1) & 3);
    }
    uint32_t bAddr[2], bMsk[2];
#pragma unroll
    for (int h2 = 0; h2 < 2; h2++) {
        const int r = ncol0 + h2 * 16 + lrow;
        bAddr[h2] = (uint32_t)(r * 64);
        bMsk[h2] = (uint32_t)((r >> 1) & 3);
    }

    issue(0, 0);
    issue(1, 1);
    issue(2, 2);

    for (int kc = 0; kc < NCH; kc++) {
        CP_WAIT2();
        __syncthreads();
        if (kc + 3 < NCH) issue(kc + 3, (kc + 3) & 3);
        else CP_COMMIT();

        const uint32_t sa = sbase + (uint32_t)((kc & 3) * STAGE_B);
#pragma unroll
        for (int ks = 0; ks < 2; ks++) {
            const uint32_t j = (uint32_t)(ks * 2) + jhalf;
            uint32_t ah[2][4], al[2][4], bh[2][4], bl[2][4];
#pragma unroll
            for (int mi = 0; mi < 2; mi++) {
                const uint32_t adr = sa + aAddr[mi] + ((j ^ aMsk[mi]) << 4);
                ldm_x4(ah[mi], adr + OFF_AHI);
                ldm_x4(al[mi], adr + OFF_ALO);
            }
#pragma unroll
            for (int h2 = 0; h2 < 2; h2++) {
                const uint32_t adr = sa + bAddr[h2] + ((j ^ bMsk[h2]) << 4);
                ldm_x4(bh[h2], adr + OFF_BHI);
                ldm_x4(bl[h2], adr + OFF_BLO);
            }
            // B frag for nj: h2 = nj>>1, sel = nj&1 -> {r[sel], r[sel+2]}
#pragma unroll
            for (int mi = 0; mi < 2; mi++)
#pragma unroll
                for (int nj = 0; nj < 4; nj++) {
                    const int h2 = nj >> 1, sl = nj & 1;
                    const uint32_t bH0 = bh[h2][sl], bH1 = bh[h2][sl + 2];
                    const uint32_t bL0 = bl[h2][sl], bL1 = bl[h2][sl + 2];
                    imma16832(acc11[mi][nj], ah[mi], bH0, bH1);
                    imma16832(accX[mi][nj], ah[mi], bL0, bL1);
                    imma16832(accX[mi][nj], al[mi], bH0, bH1);
                }
        }
    }
    CP_WAIT0();

    // ---- epilogue ----
    const int lr = lid >> 2;
    const int c2 = (lid & 3) * 2;
    const float* __restrict__ bb = bias + (size_t)e * NCOLS + (size_t)ntile * BN;
    const float* __restrict__ sw = sB + (size_t)e * NCOLS + (size_t)ntile * BN;

#pragma unroll
    for (int mi = 0; mi < 2; mi++) {
#pragma unroll
        for (int half = 0; half < 2; half++) {
            const int rloc = mrow0 + mi * 16 + lr + half * 8;
            const int grow = row0 + rloc;
            if (grow < cnt) {
                const long long tok = idx[grow];
                const float sx = sA[tok];
#pragma unroll
                for (int nj = 0; nj < 4; nj++) {
                    const int col = ncol0 + nj * 8 + c2;
                    const float d0 = (float)acc11[mi][nj][half * 2 + 0] * 16384.f
                                   + (float)accX[mi][nj][half * 2 + 0] * 128.f;
                    const float d1 = (float)acc11[mi][nj][half * 2 + 1] * 16384.f
                                   + (float)accX[mi][nj][half * 2 + 1] * 128.f;
                    const float v0 = d0 * sx * sw[col];
                    const float v1 = d1 * sx * sw[col + 1];
                    if (IS_G1) {
                        float r0 = v0 + bb[col];
                        float r1 = v1 + bb[col + 1];
                        r0 = r0 > 0.f ? r0 : 0.f;
                        r1 = r1 > 0.f ? r1 : 0.f;
                        *(float2*)(g_h + (size_t)tok * MID + (size_t)ntile * BN + col) =
                            make_float2(r0, r1);
                    } else {
                        const size_t o = (size_t)tok * DIM + (size_t)ntile * BN + col;
                        float2 xv = *(const float2*)(x + o);
                        *(float2*)(out + o) =
                            make_float2(xv.x + v0 + bb[col], xv.y + v1 + bb[col + 1]);
                    }
                }
            }
        }
    }
}

// ---------------- host launch ----------------
extern "C" void kernel_launch(void* const* d_in, const int* in_sizes, int n_in,
                              void* d_out, int out_size) {
    const float* x       = (const float*)d_in[0];
    const void*  domains = d_in[1];
    const float* W1      = (const float*)d_in[2];
    const float* b1      = (const float*)d_in[3];
    const float* W2      = (const float*)d_in[4];
    const float* b2      = (const float*)d_in[5];
    float*       out     = (float*)d_out;

    detect_dtype_kernel<<<1, 32>>>((const int*)domains);
    zero_counts_kernel<<<1, 32>>>();
    bucket_kernel<<<(N_TOK + 255) / 256, 256>>>(domains);

    int8_t *x1, *x0, *w11, *w10, *w21, *w20, *h1, *h0;
    float *sx, *sw1, *sw2, *sh, *hbuf;
    cudaGetSymbolAddress((void**)&x1,  g_x1);
    cudaGetSymbolAddress((void**)&x0,  g_x0);
    cudaGetSymbolAddress((void**)&w11, g_w11);
    cudaGetSymbolAddress((void**)&w10, g_w10);
    cudaGetSymbolAddress((void**)&w21, g_w21);
    cudaGetSymbolAddress((void**)&w20, g_w20);
    cudaGetSymbolAddress((void**)&h1,  g_h1);
    cudaGetSymbolAddress((void**)&h0,  g_h0);
    cudaGetSymbolAddress((void**)&sx,  g_sx);
    cudaGetSymbolAddress((void**)&sw1, g_sw1);
    cudaGetSymbolAddress((void**)&sw2, g_sw2);
    cudaGetSymbolAddress((void**)&sh,  g_sh);
    cudaGetSymbolAddress((void**)&hbuf, g_h);

    quant_rows_kernel<<<N_TOK, 128>>>(x, x1, x0, sx, DIM);
    quant_rows_kernel<<<NEXP * MID, 128>>>(W1, w11, w10, sw1, DIM);
    quant_rows_kernel<<<NEXP * DIM, 128>>>(W2, w21, w20, sw2, MID);

    cudaFuncSetAttribute(moe_gemm_kernel<DIM, true>,
                         cudaFuncAttributeMaxDynamicSharedMemorySize, SMEM_TOT);
    cudaFuncSetAttribute(moe_gemm_kernel<MID, false>,
                         cudaFuncAttributeMaxDynamicSharedMemorySize, SMEM_TOT);

    dim3 grid1(NEXP * (N_TOK / BM), MID / BN);   // (256, 8)
    moe_gemm_kernel<DIM, true><<<grid1, 256, SMEM_TOT>>>(
        x, x1, x0, sx, w11, w10, sw1, b1, nullptr);

    quant_rows_kernel<<<N_TOK, 128>>>(hbuf, h1, h0, sh, MID);

    dim3 grid2(NEXP * (N_TOK / BM), DIM / BN);   // (256, 32)
    moe_gemm_kernel<MID, false><<<grid2, 256, SMEM_TOT>>>(
        x, h1, h0, sh, w21, w20, sw2, b2, out);
}

// round 7
// speedup vs baseline: 2.8916x; 2.8916x over previous
#include <cuda_runtime.h>
#include <cuda_fp16.h>
#include <cstdint>

#define N_TOK 8192
#define DIM   2048
#define MID   512
#define NEXP  4

#define BM 128
#define BN 64
#define KC 32                        // fp16 K elems per chunk (64 B rows)
#define A_TILE_B (128 * 64)          // 8 KB
#define B_TILE_B (64 * 64)           // 4 KB
#define OFF_AHI 0
#define OFF_ALO (A_TILE_B)
#define OFF_B   (2 * A_TILE_B)
#define STAGE_B (2 * A_TILE_B + B_TILE_B)   // 20 KB
#define NSTAGE 4
#define SMEM_TOT (NSTAGE * STAGE_B)  // 80 KB

// ---------------- device scratch ----------------
__device__ int g_counts[NEXP];
__device__ int g_idx[NEXP * N_TOK];
__device__ int g_is64;
__device__ __half g_x_hi[(size_t)N_TOK * DIM];
__device__ __half g_x_lo[(size_t)N_TOK * DIM];
__device__ __half g_w1[(size_t)NEXP * MID * DIM];
__device__ __half g_w2[(size_t)NEXP * DIM * MID];
__device__ __half g_h_hi[(size_t)N_TOK * MID];
__device__ __half g_h_lo[(size_t)N_TOK * MID];

// ---------------- helpers ----------------
__device__ __forceinline__ uint32_t smem_u32(const void* p) {
    uint32_t a;
    asm("{ .reg .u64 t; cvta.to.shared.u64 t, %1; cvt.u32.u64 %0, t; }" : "=r"(a) : "l"(p));
    return a;
}
__device__ __forceinline__ void ldm_x4(uint32_t* r, uint32_t addr) {
    asm volatile("ldmatrix.sync.aligned.m8n8.x4.shared.b16 {%0,%1,%2,%3}, [%4];"
                 : "=r"(r[0]), "=r"(r[1]), "=r"(r[2]), "=r"(r[3]) : "r"(addr));
}
__device__ __forceinline__ void mma16816h(float* c, const uint32_t* a, const uint32_t* b) {
    asm volatile("mma.sync.aligned.m16n8k16.row.col.f32.f16.f16.f32 "
                 "{%0,%1,%2,%3}, {%4,%5,%6,%7}, {%8,%9}, {%0,%1,%2,%3};"
                 : "+f"(c[0]), "+f"(c[1]), "+f"(c[2]), "+f"(c[3])
                 : "r"(a[0]), "r"(a[1]), "r"(a[2]), "r"(a[3]), "r"(b[0]), "r"(b[1]));
}
#define CP_ASYNC16(dst, src) \
    asm volatile("cp.async.cg.shared.global [%0], [%1], 16;" :: "r"(dst), "l"(src))
#define CP_ASYNC16_Z(dst, src, zb) \
    asm volatile("cp.async.cg.shared.global [%0], [%1], 16, %2;" :: "r"(dst), "l"(src), "r"(zb))
#define CP_COMMIT() asm volatile("cp.async.commit_group;" ::: "memory")
#define CP_WAIT2()  asm volatile("cp.async.wait_group 2;" ::: "memory")
#define CP_WAIT0()  asm volatile("cp.async.wait_group 0;" ::: "memory")

// split two fp32 into packed fp16 hi pair + lo pair
__device__ __forceinline__ void split2h(float a, float b, uint32_t& hi, uint32_t& lo) {
    __half ha = __float2half_rn(a), hb = __float2half_rn(b);
    float ra = a - __half2float(ha);
    float rb = b - __half2float(hb);
    __half2 H(ha, hb);
    __half2 L(__float2half_rn(ra), __float2half_rn(rb));
    hi = *reinterpret_cast<uint32_t*>(&H);
    lo = *reinterpret_cast<uint32_t*>(&L);
}

// ---------------- setup kernels ----------------
__global__ void detect_dtype_kernel(const int* __restrict__ dom32) {
    if (threadIdx.x == 0) {
        int odd_zero = 1;
        for (int i = 1; i < 512; i += 2)
            if (dom32[i] != 0) { odd_zero = 0; break; }
        g_is64 = odd_zero;
    }
}
__global__ void zero_counts_kernel() { if (threadIdx.x < NEXP) g_counts[threadIdx.x] = 0; }

__global__ void bucket_kernel(const void* __restrict__ dom) {
    int n = blockIdx.x * blockDim.x + threadIdx.x;
    if (n >= N_TOK) return;
    int e = g_is64 ? (int)((const long long*)dom)[n] : ((const int*)dom)[n];
    int p = atomicAdd(&g_counts[e], 1);
    g_idx[e * N_TOK + p] = n;
}

// fp32 -> fp16 hi/lo split
__global__ void split_kernel(const float* __restrict__ src,
                             __half* __restrict__ hi,
                             __half* __restrict__ lo, int n4) {
    int i = blockIdx.x * blockDim.x + threadIdx.x;
    int stride = gridDim.x * blockDim.x;
    for (; i < n4; i += stride) {
        float4 v = ((const float4*)src)[i];
        uint32_t h0, h1, l0, l1;
        split2h(v.x, v.y, h0, l0);
        split2h(v.z, v.w, h1, l1);
        ((uint2*)hi)[i] = make_uint2(h0, h1);
        ((uint2*)lo)[i] = make_uint2(l0, l1);
    }
}

// fp32 -> fp16 single
__global__ void cvt_kernel(const float* __restrict__ src, __half* __restrict__ dst, int n4) {
    int i = blockIdx.x * blockDim.x + threadIdx.x;
    int stride = gridDim.x * blockDim.x;
    for (; i < n4; i += stride) {
        float4 v = ((const float4*)src)[i];
        __half2 a(__float2half_rn(v.x), __float2half_rn(v.y));
        __half2 b(__float2half_rn(v.z), __float2half_rn(v.w));
        ((uint2*)dst)[i] = make_uint2(*reinterpret_cast<uint32_t*>(&a),
                                      *reinterpret_cast<uint32_t*>(&b));
    }
}

// ---------------- grouped GEMM: 4-stage cp.async + fp16 2-term mma ----------------
// BM=128 x BN=64; 8 warps 4(m) x 2(n); warp tile 32x32.
template <int KDIM, bool IS_G1>
__global__ __launch_bounds__(256, 2)
void moe_gemm_kernel(const float* __restrict__ x,
                     const __half* __restrict__ A_hi,
                     const __half* __restrict__ A_lo,
                     const __half* __restrict__ B_h,
                     const float* __restrict__ bias,
                     float* __restrict__ out) {
    constexpr int NCH   = KDIM / KC;
    constexpr int NCOLS = IS_G1 ? MID : DIM;

    const int tiles_per_e = N_TOK / BM;            // 64
    const int e     = blockIdx.x / tiles_per_e;
    const int mtile = blockIdx.x % tiles_per_e;
    const int ntile = blockIdx.y;

    const int cnt  = g_counts[e];
    const int row0 = mtile * BM;
    if (row0 >= cnt) return;
    const int* __restrict__ idx = g_idx + e * N_TOK;

    extern __shared__ char smem[];
    const uint32_t sbase = smem_u32(smem);

    const int tid = threadIdx.x;
    const int wid = tid >> 5;
    const int lid = tid & 31;
    const int mrow0 = (wid & 3) * 32;
    const int ncol0 = (wid >> 2) * 32;

    // ---- cp.async fill mapping: 64 B rows = 4 x 16 B chunks ----
    const int c4 = tid & 3;
    const __half* ahp[2];
    uint32_t zbA[2];
    uint32_t stsA[2];
#pragma unroll
    for (int i = 0; i < 2; i++) {
        const int row = (tid >> 2) + 64 * i;
        const int grow = row0 + row;
        const bool live = (grow < cnt);
        ahp[i] = live ? A_hi + (size_t)idx[grow] * KDIM + c4 * 8 : A_hi;
        zbA[i] = live ? 16u : 0u;
        stsA[i] = (uint32_t)(row * 64 + ((c4 ^ ((row >> 1) & 3)) << 4));
    }
    const int brow = tid >> 2;
    const size_t boff = ((size_t)e * NCOLS + (size_t)ntile * BN + brow) * KDIM + c4 * 8;
    const uint32_t stsB = (uint32_t)(brow * 64 + ((c4 ^ ((brow >> 1) & 3)) << 4));
    const ptrdiff_t alo_d = A_lo - A_hi;

    auto issue = [&](int ch, int slot) {
        const int k0 = ch * KC;
        const uint32_t st = sbase + (uint32_t)(slot * STAGE_B);
#pragma unroll
        for (int i = 0; i < 2; i++) {
            CP_ASYNC16_Z(st + OFF_AHI + stsA[i], ahp[i] + k0, zbA[i]);
            CP_ASYNC16_Z(st + OFF_ALO + stsA[i], ahp[i] + alo_d + k0, zbA[i]);
        }
        CP_ASYNC16(st + OFF_B + stsB, B_h + boff + k0);
        CP_COMMIT();
    };

    float acc[2][4][4];
#pragma unroll
    for (int mi = 0; mi < 2; mi++)
#pragma unroll
        for (int nj = 0; nj < 4; nj++)
#pragma unroll
            for (int q = 0; q < 4; q++) acc[mi][nj][q] = 0.f;

    // ---- ldmatrix per-lane addresses ----
    uint32_t aRow[2], aMsk[2];
#pragma unroll
    for (int mi = 0; mi < 2; mi++) {
        const int r = mrow0 + mi * 16 + (lid & 15);
        aRow[mi] = (uint32_t)(r * 64);
        aMsk[mi] = (uint32_t)((r >> 1) & 3);
    }
    const uint32_t ja = (uint32_t)(lid >> 4);
    uint32_t bRow[2], bMsk[2];
#pragma unroll
    for (int h2 = 0; h2 < 2; h2++) {
        const int r = ncol0 + h2 * 16 + (lid & 7) + 8 * (lid >> 4);
        bRow[h2] = (uint32_t)(r * 64);
        bMsk[h2] = (uint32_t)((r >> 1) & 3);
    }
    const uint32_t jb = (uint32_t)((lid >> 3) & 1);

    issue(0, 0);
    issue(1, 1);
    issue(2, 2);

    for (int kc = 0; kc < NCH; kc++) {
        CP_WAIT2();
        __syncthreads();
        if (kc + 3 < NCH) issue(kc + 3, (kc + 3) & 3);
        else CP_COMMIT();

        const uint32_t sa = sbase + (uint32_t)((kc & 3) * STAGE_B);
#pragma unroll
        for (int ks = 0; ks < 2; ks++) {
            uint32_t ah[2][4], al[2][4], bf[2][4];
#pragma unroll
            for (int mi = 0; mi < 2; mi++) {
                const uint32_t adr = sa + aRow[mi] + ((((uint32_t)(2 * ks) + ja) ^ aMsk[mi]) << 4);
                ldm_x4(ah[mi], adr + OFF_AHI);
                ldm_x4(al[mi], adr + OFF_ALO);
            }
#pragma unroll
            for (int h2 = 0; h2 < 2; h2++) {
                const uint32_t adr = sa + bRow[h2] + ((((uint32_t)(2 * ks) + jb) ^ bMsk[h2]) << 4);
                ldm_x4(bf[h2], adr + OFF_B);
            }
#pragma unroll
            for (int mi = 0; mi < 2; mi++)
#pragma unroll
                for (int nj = 0; nj < 4; nj++) {
                    const uint32_t* fb = &bf[nj >> 1][(nj & 1) * 2];
                    mma16816h(acc[mi][nj], ah[mi], fb);
                    mma16816h(acc[mi][nj], al[mi], fb);
                }
        }
    }
    CP_WAIT0();

    // ---- epilogue ----
    const int lr = lid >> 2;
    const int c2 = (lid & 3) * 2;
    const float* __restrict__ bb = bias + (size_t)e * NCOLS + (size_t)ntile * BN;

#pragma unroll
    for (int mi = 0; mi < 2; mi++) {
#pragma unroll
        for (int half = 0; half < 2; half++) {
            const int rloc = mrow0 + mi * 16 + lr + half * 8;
            const int grow = row0 + rloc;
            if (grow < cnt) {
                const long long tok = idx[grow];
#pragma unroll
                for (int nj = 0; nj < 4; nj++) {
                    const int col = ncol0 + nj * 8 + c2;
                    const float v0 = acc[mi][nj][half * 2 + 0];
                    const float v1 = acc[mi][nj][half * 2 + 1];
                    if (IS_G1) {
                        float r0 = v0 + bb[col];
                        float r1 = v1 + bb[col + 1];
                        r0 = r0 > 0.f ? r0 : 0.f;
                        r1 = r1 > 0.f ? r1 : 0.f;
                        uint32_t h, l;
                        split2h(r0, r1, h, l);
                        const size_t o = (size_t)tok * MID + (size_t)ntile * BN + col;
                        *(uint32_t*)(g_h_hi + o) = h;
                        *(uint32_t*)(g_h_lo + o) = l;
                    } else {
                        const size_t o = (size_t)tok * DIM + (size_t)ntile * BN + col;
                        float2 xv = *(const float2*)(x + o);
                        *(float2*)(out + o) =
                            make_float2(xv.x + v0 + bb[col], xv.y + v1 + bb[col + 1]);
                    }
                }
            }
        }
    }
}

// ---------------- host launch ----------------
extern "C" void kernel_launch(void* const* d_in, const int* in_sizes, int n_in,
                              void* d_out, int out_size) {
    const float* x       = (const float*)d_in[0];
    const void*  domains = d_in[1];
    const float* W1      = (const float*)d_in[2];
    const float* b1      = (const float*)d_in[3];
    const float* W2      = (const float*)d_in[4];
    const float* b2      = (const float*)d_in[5];
    float*       out     = (float*)d_out;

    detect_dtype_kernel<<<1, 32>>>((const int*)domains);
    zero_counts_kernel<<<1, 32>>>();
    bucket_kernel<<<(N_TOK + 255) / 256, 256>>>(domains);

    __half *xh, *xl, *w1h, *w2h, *hh, *hl;
    cudaGetSymbolAddress((void**)&xh,  g_x_hi);
    cudaGetSymbolAddress((void**)&xl,  g_x_lo);
    cudaGetSymbolAddress((void**)&w1h, g_w1);
    cudaGetSymbolAddress((void**)&w2h, g_w2);
    cudaGetSymbolAddress((void**)&hh,  g_h_hi);
    cudaGetSymbolAddress((void**)&hl,  g_h_lo);

    split_kernel<<<1024, 256>>>(x, xh, xl, (N_TOK * DIM) / 4);
    cvt_kernel<<<512, 256>>>(W1, w1h, (NEXP * MID * DIM) / 4);
    cvt_kernel<<<512, 256>>>(W2, w2h, (NEXP * DIM * MID) / 4);

    cudaFuncSetAttribute(moe_gemm_kernel<DIM, true>,
                         cudaFuncAttributeMaxDynamicSharedMemorySize, SMEM_TOT);
    cudaFuncSetAttribute(moe_gemm_kernel<MID, false>,
                         cudaFuncAttributeMaxDynamicSharedMemorySize, SMEM_TOT);

    dim3 grid1(NEXP * (N_TOK / BM), MID / BN);   // (256, 8)
    moe_gemm_kernel<DIM, true><<<grid1, 256, SMEM_TOT>>>(
        x, xh, xl, w1h, b1, nullptr);

    dim3 grid2(NEXP * (N_TOK / BM), DIM / BN);   // (256, 32)
    moe_gemm_kernel<MID, false><<<grid2, 256, SMEM_TOT>>>(
        x, hh, hl, w2h, b2, out);
}

// round 9
// speedup vs baseline: 4.9193x; 1.7013x over previous
#include <cuda_runtime.h>
#include <cuda_fp16.h>
#include <cstdint>

#define N_TOK 8192
#define DIM   2048
#define MID   512
#define NEXP  4

#define BM 128
#define BN 128
#define KC 32                        // fp16 K elems per chunk (64 B rows)
#define A_TILE_B (128 * 64)          // 8 KB
#define B_TILE_B (128 * 64)          // 8 KB
#define OFF_A 0
#define OFF_B A_TILE_B
#define STAGE_B (A_TILE_B + B_TILE_B)   // 16 KB
#define NSTAGE 4
#define SMEM_TOT (NSTAGE * STAGE_B)  // 64 KB

// ---------------- device scratch ----------------
__device__ int g_counts[NEXP];
__device__ int g_idx[NEXP * N_TOK];
__device__ int g_is64;
__device__ __half g_x[(size_t)N_TOK * DIM];
__device__ __half g_w1[(size_t)NEXP * MID * DIM];
__device__ __half g_w2[(size_t)NEXP * DIM * MID];
__device__ __half g_h[(size_t)N_TOK * MID];

// ---------------- helpers ----------------
__device__ __forceinline__ uint32_t smem_u32(const void* p) {
    uint32_t a;
    asm("{ .reg .u64 t; cvta.to.shared.u64 t, %1; cvt.u32.u64 %0, t; }" : "=r"(a) : "l"(p));
    return a;
}
__device__ __forceinline__ void ldm_x4(uint32_t* r, uint32_t addr) {
    asm volatile("ldmatrix.sync.aligned.m8n8.x4.shared.b16 {%0,%1,%2,%3}, [%4];"
                 : "=r"(r[0]), "=r"(r[1]), "=r"(r[2]), "=r"(r[3]) : "r"(addr));
}
__device__ __forceinline__ void mma16816h(float* c, const uint32_t* a, uint32_t b0, uint32_t b1) {
    asm volatile("mma.sync.aligned.m16n8k16.row.col.f32.f16.f16.f32 "
                 "{%0,%1,%2,%3}, {%4,%5,%6,%7}, {%8,%9}, {%0,%1,%2,%3};"
                 : "+f"(c[0]), "+f"(c[1]), "+f"(c[2]), "+f"(c[3])
                 : "r"(a[0]), "r"(a[1]), "r"(a[2]), "r"(a[3]), "r"(b0), "r"(b1));
}
#define CP_ASYNC16(dst, src) \
    asm volatile("cp.async.cg.shared.global [%0], [%1], 16;" :: "r"(dst), "l"(src))
#define CP_ASYNC16_Z(dst, src, zb) \
    asm volatile("cp.async.cg.shared.global [%0], [%1], 16, %2;" :: "r"(dst), "l"(src), "r"(zb))
#define CP_COMMIT() asm volatile("cp.async.commit_group;" ::: "memory")
#define CP_WAIT2()  asm volatile("cp.async.wait_group 2;" ::: "memory")
#define CP_WAIT0()  asm volatile("cp.async.wait_group 0;" ::: "memory")

// ---------------- setup kernels ----------------
__global__ void detect_dtype_kernel(const int* __restrict__ dom32) {
    if (threadIdx.x == 0) {
        int odd_zero = 1;
        for (int i = 1; i < 512; i += 2)
            if (dom32[i] != 0) { odd_zero = 0; break; }
        g_is64 = odd_zero;
    }
}
__global__ void zero_counts_kernel() { if (threadIdx.x < NEXP) g_counts[threadIdx.x] = 0; }

__global__ void bucket_kernel(const void* __restrict__ dom) {
    int n = blockIdx.x * blockDim.x + threadIdx.x;
    if (n >= N_TOK) return;
    int e = g_is64 ? (int)((const long long*)dom)[n] : ((const int*)dom)[n];
    int p = atomicAdd(&g_counts[e], 1);
    g_idx[e * N_TOK + p] = n;
}

// fp32 -> fp16
__global__ void cvt_kernel(const float* __restrict__ src, __half* __restrict__ dst, int n4) {
    int i = blockIdx.x * blockDim.x + threadIdx.x;
    int stride = gridDim.x * blockDim.x;
    for (; i < n4; i += stride) {
        float4 v = ((const float4*)src)[i];
        __half2 a(__float2half_rn(v.x), __float2half_rn(v.y));
        __half2 b(__float2half_rn(v.z), __float2half_rn(v.w));
        ((uint2*)dst)[i] = make_uint2(*reinterpret_cast<uint32_t*>(&a),
                                      *reinterpret_cast<uint32_t*>(&b));
    }
}

// ---------------- grouped GEMM: 4-stage cp.async + single-term fp16 mma ----------------
// BM=128 x BN=128; 8 warps 4(m) x 2(n); warp tile 32x64.
template <int KDIM, bool IS_G1>
__global__ __launch_bounds__(256, 2)
void moe_gemm_kernel(const float* __restrict__ x,
                     const __half* __restrict__ A_h,
                     const __half* __restrict__ B_h,
                     const float* __restrict__ bias,
                     float* __restrict__ out) {
    constexpr int NCH   = KDIM / KC;
    constexpr int NCOLS = IS_G1 ? MID : DIM;

    const int tiles_per_e = N_TOK / BM;            // 64
    const int e     = blockIdx.x / tiles_per_e;
    const int mtile = blockIdx.x % tiles_per_e;
    const int ntile = blockIdx.y;

    const int cnt  = g_counts[e];
    const int row0 = mtile * BM;
    if (row0 >= cnt) return;
    const int* __restrict__ idx = g_idx + e * N_TOK;

    extern __shared__ char smem[];
    const uint32_t sbase = smem_u32(smem);

    const int tid = threadIdx.x;
    const int wid = tid >> 5;
    const int lid = tid & 31;
    const int mrow0 = (wid & 3) * 32;
    const int ncol0 = (wid >> 2) * 64;

    // ---- cp.async fill mapping: 64 B rows = 4 x 16 B chunks; 2 rows per thread each for A,B ----
    const int c4 = tid & 3;
    const __half* ahp[2];
    const __half* bpp[2];
    uint32_t zbA[2];
    uint32_t sts[2];
#pragma unroll
    for (int i = 0; i < 2; i++) {
        const int row = (tid >> 2) + 64 * i;
        const int grow = row0 + row;
        const bool live = (grow < cnt);
        ahp[i] = live ? A_h + (size_t)idx[grow] * KDIM + c4 * 8 : A_h;
        zbA[i] = live ? 16u : 0u;
        bpp[i] = B_h + ((size_t)e * NCOLS + (size_t)ntile * BN + row) * KDIM + c4 * 8;
        sts[i] = (uint32_t)(row * 64 + ((c4 ^ ((row >> 1) & 3)) << 4));
    }

    auto issue = [&](int ch, int slot) {
        const int k0 = ch * KC;
        const uint32_t st = sbase + (uint32_t)(slot * STAGE_B);
#pragma unroll
        for (int i = 0; i < 2; i++) {
            CP_ASYNC16_Z(st + OFF_A + sts[i], ahp[i] + k0, zbA[i]);
            CP_ASYNC16(st + OFF_B + sts[i], bpp[i] + k0);
        }
        CP_COMMIT();
    };

    float acc[2][8][4];
#pragma unroll
    for (int mi = 0; mi < 2; mi++)
#pragma unroll
        for (int nj = 0; nj < 8; nj++)
#pragma unroll
            for (int q = 0; q < 4; q++) acc[mi][nj][q] = 0.f;

    // ---- ldmatrix per-lane addresses ----
    uint32_t aRow[2], aMsk[2];
#pragma unroll
    for (int mi = 0; mi < 2; mi++) {
        const int r = mrow0 + mi * 16 + (lid & 15);
        aRow[mi] = (uint32_t)(r * 64);
        aMsk[mi] = (uint32_t)((r >> 1) & 3);
    }
    const uint32_t ja = (uint32_t)(lid >> 4);
    uint32_t bRow[4], bMsk[4];
#pragma unroll
    for (int h2 = 0; h2 < 4; h2++) {
        const int r = ncol0 + h2 * 16 + (lid & 7) + 8 * (lid >> 4);
        bRow[h2] = (uint32_t)(r * 64);
        bMsk[h2] = (uint32_t)((r >> 1) & 3);
    }
    const uint32_t jb = (uint32_t)((lid >> 3) & 1);

    issue(0, 0);
    issue(1, 1);
    issue(2, 2);

    for (int kc = 0; kc < NCH; kc++) {
        CP_WAIT2();
        __syncthreads();
        if (kc + 3 < NCH) issue(kc + 3, (kc + 3) & 3);
        else CP_COMMIT();

        const uint32_t sa = sbase + (uint32_t)((kc & 3) * STAGE_B);
#pragma unroll
        for (int ks = 0; ks < 2; ks++) {
            uint32_t ah[2][4], bf[4][4];
#pragma unroll
            for (int mi = 0; mi < 2; mi++) {
                const uint32_t adr = sa + aRow[mi] + ((((uint32_t)(2 * ks) + ja) ^ aMsk[mi]) << 4);
                ldm_x4(ah[mi], adr + OFF_A);
            }
#pragma unroll
            for (int h2 = 0; h2 < 4; h2++) {
                const uint32_t adr = sa + bRow[h2] + ((((uint32_t)(2 * ks) + jb) ^ bMsk[h2]) << 4);
                ldm_x4(bf[h2], adr + OFF_B);
            }
#pragma unroll
            for (int mi = 0; mi < 2; mi++)
#pragma unroll
                for (int nj = 0; nj < 8; nj++) {
                    const int h2 = nj >> 1, sl = nj & 1;
                    // B k0/k1 register pair for n-group sl is {2*sl, 2*sl+1}
                    mma16816h(acc[mi][nj], ah[mi], bf[h2][2 * sl], bf[h2][2 * sl + 1]);
                }
        }
    }
    CP_WAIT0();

    // ---- epilogue ----
    const int lr = lid >> 2;
    const int c2 = (lid & 3) * 2;
    const float* __restrict__ bb = bias + (size_t)e * NCOLS + (size_t)ntile * BN;

#pragma unroll
    for (int mi = 0; mi < 2; mi++) {
#pragma unroll
        for (int half = 0; half < 2; half++) {
            const int rloc = mrow0 + mi * 16 + lr + half * 8;
            const int grow = row0 + rloc;
            if (grow < cnt) {
                const long long tok = idx[grow];
#pragma unroll
                for (int nj = 0; nj < 8; nj++) {
                    const int col = ncol0 + nj * 8 + c2;
                    const float v0 = acc[mi][nj][half * 2 + 0];
                    const float v1 = acc[mi][nj][half * 2 + 1];
                    if (IS_G1) {
                        float r0 = v0 + bb[col];
                        float r1 = v1 + bb[col + 1];
                        r0 = r0 > 0.f ? r0 : 0.f;
                        r1 = r1 > 0.f ? r1 : 0.f;
                        __half2 hv(__float2half_rn(r0), __float2half_rn(r1));
                        *(uint32_t*)(g_h + (size_t)tok * MID + (size_t)ntile * BN + col) =
                            *reinterpret_cast<uint32_t*>(&hv);
                    } else {
                        const size_t o = (size_t)tok * DIM + (size_t)ntile * BN + col;
                        float2 xv = *(const float2*)(x + o);
                        *(float2*)(out + o) =
                            make_float2(xv.x + v0 + bb[col], xv.y + v1 + bb[col + 1]);
                    }
                }
            }
        }
    }
}

// ---------------- host launch ----------------
extern "C" void kernel_launch(void* const* d_in, const int* in_sizes, int n_in,
                              void* d_out, int out_size) {
    const float* x       = (const float*)d_in[0];
    const void*  domains = d_in[1];
    const float* W1      = (const float*)d_in[2];
    const float* b1      = (const float*)d_in[3];
    const float* W2      = (const float*)d_in[4];
    const float* b2      = (const float*)d_in[5];
    float*       out     = (float*)d_out;

    detect_dtype_kernel<<<1, 32>>>((const int*)domains);
    zero_counts_kernel<<<1, 32>>>();
    bucket_kernel<<<(N_TOK + 255) / 256, 256>>>(domains);

    __half *xh, *w1h, *w2h, *hh;
    cudaGetSymbolAddress((void**)&xh,  g_x);
    cudaGetSymbolAddress((void**)&w1h, g_w1);
    cudaGetSymbolAddress((void**)&w2h, g_w2);
    cudaGetSymbolAddress((void**)&hh,  g_h);

    cvt_kernel<<<1024, 256>>>(x, xh, (N_TOK * DIM) / 4);
    cvt_kernel<<<512, 256>>>(W1, w1h, (NEXP * MID * DIM) / 4);
    cvt_kernel<<<512, 256>>>(W2, w2h, (NEXP * DIM * MID) / 4);

    cudaFuncSetAttribute(moe_gemm_kernel<DIM, true>,
                         cudaFuncAttributeMaxDynamicSharedMemorySize, SMEM_TOT);
    cudaFuncSetAttribute(moe_gemm_kernel<MID, false>,
                         cudaFuncAttributeMaxDynamicSharedMemorySize, SMEM_TOT);

    dim3 grid1(NEXP * (N_TOK / BM), MID / BN);   // (256, 4)
    moe_gemm_kernel<DIM, true><<<grid1, 256, SMEM_TOT>>>(x, xh, w1h, b1, nullptr);

    dim3 grid2(NEXP * (N_TOK / BM), DIM / BN);   // (256, 16)
    moe_gemm_kernel<MID, false><<<grid2, 256, SMEM_TOT>>>(x, hh, w2h, b2, out);
}

// round 10
// speedup vs baseline: 5.2656x; 1.0704x over previous
#include <cuda_runtime.h>
#include <cuda_fp16.h>
#include <cstdint>

#define N_TOK 8192
#define DIM   2048
#define MID   512
#define NEXP  4

#define BM 128
#define BN 128
#define KC 64                        // fp16 K elems per chunk (128 B rows)
#define A_TILE_B (128 * 128)         // 16 KB
#define B_TILE_B (128 * 128)         // 16 KB
#define OFF_A 0
#define OFF_B A_TILE_B
#define STAGE_B (A_TILE_B + B_TILE_B)   // 32 KB
#define NSTAGE 3
#define SMEM_TOT (NSTAGE * STAGE_B)  // 96 KB

// ---------------- device scratch ----------------
__device__ int g_counts[NEXP];
__device__ int g_idx[NEXP * N_TOK];
__device__ int g_is64;
__device__ __half g_x[(size_t)N_TOK * DIM];
__device__ __half g_w1[(size_t)NEXP * MID * DIM];
__device__ __half g_w2[(size_t)NEXP * DIM * MID];
__device__ __half g_h[(size_t)N_TOK * MID];

// ---------------- helpers ----------------
__device__ __forceinline__ uint32_t smem_u32(const void* p) {
    uint32_t a;
    asm("{ .reg .u64 t; cvta.to.shared.u64 t, %1; cvt.u32.u64 %0, t; }" : "=r"(a) : "l"(p));
    return a;
}
__device__ __forceinline__ void ldm_x4(uint32_t* r, uint32_t addr) {
    asm volatile("ldmatrix.sync.aligned.m8n8.x4.shared.b16 {%0,%1,%2,%3}, [%4];"
                 : "=r"(r[0]), "=r"(r[1]), "=r"(r[2]), "=r"(r[3]) : "r"(addr));
}
__device__ __forceinline__ void mma16816h(float* c, const uint32_t* a, uint32_t b0, uint32_t b1) {
    asm volatile("mma.sync.aligned.m16n8k16.row.col.f32.f16.f16.f32 "
                 "{%0,%1,%2,%3}, {%4,%5,%6,%7}, {%8,%9}, {%0,%1,%2,%3};"
                 : "+f"(c[0]), "+f"(c[1]), "+f"(c[2]), "+f"(c[3])
                 : "r"(a[0]), "r"(a[1]), "r"(a[2]), "r"(a[3]), "r"(b0), "r"(b1));
}
#define CP_ASYNC16(dst, src) \
    asm volatile("cp.async.cg.shared.global [%0], [%1], 16;" :: "r"(dst), "l"(src))
#define CP_ASYNC16_Z(dst, src, zb) \
    asm volatile("cp.async.cg.shared.global [%0], [%1], 16, %2;" :: "r"(dst), "l"(src), "r"(zb))
#define CP_COMMIT() asm volatile("cp.async.commit_group;" ::: "memory")
#define CP_WAIT1()  asm volatile("cp.async.wait_group 1;" ::: "memory")
#define CP_WAIT0()  asm volatile("cp.async.wait_group 0;" ::: "memory")

// ---------------- setup kernels ----------------
__global__ void detect_dtype_kernel(const int* __restrict__ dom32) {
    if (threadIdx.x == 0) {
        int odd_zero = 1;
        for (int i = 1; i < 512; i += 2)
            if (dom32[i] != 0) { odd_zero = 0; break; }
        g_is64 = odd_zero;
    }
}
__global__ void zero_counts_kernel() { if (threadIdx.x < NEXP) g_counts[threadIdx.x] = 0; }

__global__ void bucket_kernel(const void* __restrict__ dom) {
    int n = blockIdx.x * blockDim.x + threadIdx.x;
    if (n >= N_TOK) return;
    int e = g_is64 ? (int)((const long long*)dom)[n] : ((const int*)dom)[n];
    int p = atomicAdd(&g_counts[e], 1);
    g_idx[e * N_TOK + p] = n;
}

// fused fp32 -> fp16 for x, W1, W2 (single launch, grid-stride over concatenation)
#define NX4  ((N_TOK * DIM) / 4)
#define NW14 ((NEXP * MID * DIM) / 4)
#define NW24 ((NEXP * DIM * MID) / 4)
__global__ void cvt_all_kernel(const float* __restrict__ x,
                               const float* __restrict__ w1,
                               const float* __restrict__ w2,
                               __half* __restrict__ xd,
                               __half* __restrict__ w1d,
                               __half* __restrict__ w2d) {
    int i = blockIdx.x * blockDim.x + threadIdx.x;
    const int stride = gridDim.x * blockDim.x;
    const int total = NX4 + NW14 + NW24;
    for (; i < total; i += stride) {
        const float* s;
        __half* d;
        int j;
        if (i < NX4)              { s = x;  d = xd;  j = i; }
        else if (i < NX4 + NW14)  { s = w1; d = w1d; j = i - NX4; }
        else                      { s = w2; d = w2d; j = i - NX4 - NW14; }
        float4 v = ((const float4*)s)[j];
        __half2 a(__float2half_rn(v.x), __float2half_rn(v.y));
        __half2 b(__float2half_rn(v.z), __float2half_rn(v.w));
        ((uint2*)d)[j] = make_uint2(*reinterpret_cast<uint32_t*>(&a),
                                    *reinterpret_cast<uint32_t*>(&b));
    }
}

// ---------------- grouped GEMM: 3-stage cp.async + single-term fp16 mma ----------------
// BM=128 x BN=128; 8 warps 4(m) x 2(n); warp tile 32x64. K chunks of 64 (128 B rows).
template <int KDIM, bool IS_G1>
__global__ __launch_bounds__(256, 2)
void moe_gemm_kernel(const float* __restrict__ x,
                     const __half* __restrict__ A_h,
                     const __half* __restrict__ B_h,
                     const float* __restrict__ bias,
                     float* __restrict__ out) {
    constexpr int NCH   = KDIM / KC;
    constexpr int NCOLS = IS_G1 ? MID : DIM;

    const int tiles_per_e = N_TOK / BM;            // 64
    const int e     = blockIdx.x / tiles_per_e;
    const int mtile = blockIdx.x % tiles_per_e;
    const int ntile = blockIdx.y;

    const int cnt  = g_counts[e];
    const int row0 = mtile * BM;
    if (row0 >= cnt) return;
    const int* __restrict__ idx = g_idx + e * N_TOK;

    extern __shared__ char smem[];
    const uint32_t sbase = smem_u32(smem);

    const int tid = threadIdx.x;
    const int wid = tid >> 5;
    const int lid = tid & 31;
    const int mrow0 = (wid & 3) * 32;
    const int ncol0 = (wid >> 2) * 64;

    // ---- cp.async fill mapping: 128 B rows = 8 x 16 B chunks; 256 threads.
    // thread -> c8 = tid&7, base row = tid>>3 (0..31); 4 rows strided 32 for A and for B.
    const int c8 = tid & 7;
    const __half* ahp[4];
    const __half* bpp[4];
    uint32_t zbA[4];
    uint32_t sts[4];
#pragma unroll
    for (int i = 0; i < 4; i++) {
        const int row = (tid >> 3) + 32 * i;
        const int grow = row0 + row;
        const bool live = (grow < cnt);
        ahp[i] = live ? A_h + (size_t)idx[grow] * KDIM + c8 * 8 : A_h;
        zbA[i] = live ? 16u : 0u;
        bpp[i] = B_h + ((size_t)e * NCOLS + (size_t)ntile * BN + row) * KDIM + c8 * 8;
        sts[i] = (uint32_t)(row * 128 + ((c8 ^ (row & 7)) << 4));
    }

    auto issue = [&](int ch, int slot) {
        const int k0 = ch * KC;
        const uint32_t st = sbase + (uint32_t)(slot * STAGE_B);
#pragma unroll
        for (int i = 0; i < 4; i++) {
            CP_ASYNC16_Z(st + OFF_A + sts[i], ahp[i] + k0, zbA[i]);
            CP_ASYNC16(st + OFF_B + sts[i], bpp[i] + k0);
        }
        CP_COMMIT();
    };

    float acc[2][8][4];
#pragma unroll
    for (int mi = 0; mi < 2; mi++)
#pragma unroll
        for (int nj = 0; nj < 8; nj++)
#pragma unroll
            for (int q = 0; q < 4; q++) acc[mi][nj][q] = 0.f;

    // ---- ldmatrix per-lane addresses (128 B rows, mask = row&7) ----
    uint32_t aRow[2], aMsk[2];
#pragma unroll
    for (int mi = 0; mi < 2; mi++) {
        const int r = mrow0 + mi * 16 + (lid & 15);
        aRow[mi] = (uint32_t)(r * 128);
        aMsk[mi] = (uint32_t)(r & 7);
    }
    const uint32_t ja = (uint32_t)(lid >> 4);
    uint32_t bRow[4], bMsk[4];
#pragma unroll
    for (int h2 = 0; h2 < 4; h2++) {
        const int r = ncol0 + h2 * 16 + (lid & 7) + 8 * (lid >> 4);
        bRow[h2] = (uint32_t)(r * 128);
        bMsk[h2] = (uint32_t)(r & 7);
    }
    const uint32_t jb = (uint32_t)((lid >> 3) & 1);

    issue(0, 0);
    issue(1, 1);

    int slot = 0;                       // slot of chunk kc
    for (int kc = 0; kc < NCH; kc++) {
        CP_WAIT1();
        __syncthreads();
        if (kc + 2 < NCH) {
            int s2 = slot + 2;
            if (s2 >= NSTAGE) s2 -= NSTAGE;
            issue(kc + 2, s2);
        } else {
            CP_COMMIT();
        }

        const uint32_t sa = sbase + (uint32_t)(slot * STAGE_B);
#pragma unroll
        for (int ks = 0; ks < 4; ks++) {
            uint32_t ah[2][4], bf[4][4];
#pragma unroll
            for (int mi = 0; mi < 2; mi++) {
                const uint32_t adr = sa + aRow[mi] + ((((uint32_t)(2 * ks) + ja) ^ aMsk[mi]) << 4);
                ldm_x4(ah[mi], adr + OFF_A);
            }
#pragma unroll
            for (int h2 = 0; h2 < 4; h2++) {
                const uint32_t adr = sa + bRow[h2] + ((((uint32_t)(2 * ks) + jb) ^ bMsk[h2]) << 4);
                ldm_x4(bf[h2], adr + OFF_B);
            }
#pragma unroll
            for (int mi = 0; mi < 2; mi++)
#pragma unroll
                for (int nj = 0; nj < 8; nj++) {
                    const int h2 = nj >> 1, sl = nj & 1;
                    mma16816h(acc[mi][nj], ah[mi], bf[h2][2 * sl], bf[h2][2 * sl + 1]);
                }
        }
        if (++slot == NSTAGE) slot = 0;
    }
    CP_WAIT0();

    // ---- epilogue ----
    const int lr = lid >> 2;
    const int c2 = (lid & 3) * 2;
    const float* __restrict__ bb = bias + (size_t)e * NCOLS + (size_t)ntile * BN;

#pragma unroll
    for (int mi = 0; mi < 2; mi++) {
#pragma unroll
        for (int half = 0; half < 2; half++) {
            const int rloc = mrow0 + mi * 16 + lr + half * 8;
            const int grow = row0 + rloc;
            if (grow < cnt) {
                const long long tok = idx[grow];
#pragma unroll
                for (int nj = 0; nj < 8; nj++) {
                    const int col = ncol0 + nj * 8 + c2;
                    const float v0 = acc[mi][nj][half * 2 + 0];
                    const float v1 = acc[mi][nj][half * 2 + 1];
                    if (IS_G1) {
                        float r0 = v0 + bb[col];
                        float r1 = v1 + bb[col + 1];
                        r0 = r0 > 0.f ? r0 : 0.f;
                        r1 = r1 > 0.f ? r1 : 0.f;
                        __half2 hv(__float2half_rn(r0), __float2half_rn(r1));
                        *(uint32_t*)(g_h + (size_t)tok * MID + (size_t)ntile * BN + col) =
                            *reinterpret_cast<uint32_t*>(&hv);
                    } else {
                        const size_t o = (size_t)tok * DIM + (size_t)ntile * BN + col;
                        float2 xv = *(const float2*)(x + o);
                        *(float2*)(out + o) =
                            make_float2(xv.x + v0 + bb[col], xv.y + v1 + bb[col + 1]);
                    }
                }
            }
        }
    }
}

// ---------------- host launch ----------------
extern "C" void kernel_launch(void* const* d_in, const int* in_sizes, int n_in,
                              void* d_out, int out_size) {
    const float* x       = (const float*)d_in[0];
    const void*  domains = d_in[1];
    const float* W1      = (const float*)d_in[2];
    const float* b1      = (const float*)d_in[3];
    const float* W2      = (const float*)d_in[4];
    const float* b2      = (const float*)d_in[5];
    float*       out     = (float*)d_out;

    detect_dtype_kernel<<<1, 32>>>((const int*)domains);
    zero_counts_kernel<<<1, 32>>>();
    bucket_kernel<<<(N_TOK + 255) / 256, 256>>>(domains);

    __half *xh, *w1h, *w2h, *hh;
    cudaGetSymbolAddress((void**)&xh,  g_x);
    cudaGetSymbolAddress((void**)&w1h, g_w1);
    cudaGetSymbolAddress((void**)&w2h, g_w2);
    cudaGetSymbolAddress((void**)&hh,  g_h);

    cvt_all_kernel<<<2048, 256>>>(x, W1, W2, xh, w1h, w2h);

    cudaFuncSetAttribute(moe_gemm_kernel<DIM, true>,
                         cudaFuncAttributeMaxDynamicSharedMemorySize, SMEM_TOT);
    cudaFuncSetAttribute(moe_gemm_kernel<MID, false>,
                         cudaFuncAttributeMaxDynamicSharedMemorySize, SMEM_TOT);

    dim3 grid1(NEXP * (N_TOK / BM), MID / BN);   // (256, 4)
    moe_gemm_kernel<DIM, true><<<grid1, 256, SMEM_TOT>>>(x, xh, w1h, b1, nullptr);

    dim3 grid2(NEXP * (N_TOK / BM), DIM / BN);   // (256, 16)
    moe_gemm_kernel<MID, false><<<grid2, 256, SMEM_TOT>>>(x, hh, w2h, b2, out);
}

// round 12
// speedup vs baseline: 5.4128x; 1.0280x over previous
#include <cuda_runtime.h>
#include <cuda_fp16.h>
#include <cstdint>

#define N_TOK 8192
#define DIM   2048
#define MID   512
#define NEXP  4

#define BM 128
#define BN 128
#define KC 64                        // fp16 K elems per chunk (128 B rows)
#define A_TILE_B (128 * 128)         // 16 KB
#define B_TILE_B (128 * 128)         // 16 KB
#define OFF_A 0
#define OFF_B A_TILE_B
#define STAGE_B (A_TILE_B + B_TILE_B)   // 32 KB
#define NSTAGE 3
#define SMEM_TOT (NSTAGE * STAGE_B)  // 96 KB

// ---------------- device scratch ----------------
__device__ int g_counts[NEXP];
__device__ int g_idx[NEXP * N_TOK];
__device__ int g_is64;
__device__ __half g_x[(size_t)N_TOK * DIM];
__device__ __half g_w1[(size_t)NEXP * MID * DIM];
__device__ __half g_w2[(size_t)NEXP * DIM * MID];
__device__ __half g_h[(size_t)N_TOK * MID];

// ---------------- helpers ----------------
__device__ __forceinline__ uint32_t smem_u32(const void* p) {
    uint32_t a;
    asm("{ .reg .u64 t; cvta.to.shared.u64 t, %1; cvt.u32.u64 %0, t; }" : "=r"(a) : "l"(p));
    return a;
}
__device__ __forceinline__ void ldm_x4(uint32_t* r, uint32_t addr) {
    asm volatile("ldmatrix.sync.aligned.m8n8.x4.shared.b16 {%0,%1,%2,%3}, [%4];"
                 : "=r"(r[0]), "=r"(r[1]), "=r"(r[2]), "=r"(r[3]) : "r"(addr));
}
__device__ __forceinline__ void mma16816h(float* c, const uint32_t* a, uint32_t b0, uint32_t b1) {
    asm volatile("mma.sync.aligned.m16n8k16.row.col.f32.f16.f16.f32 "
                 "{%0,%1,%2,%3}, {%4,%5,%6,%7}, {%8,%9}, {%0,%1,%2,%3};"
                 : "+f"(c[0]), "+f"(c[1]), "+f"(c[2]), "+f"(c[3])
                 : "r"(a[0]), "r"(a[1]), "r"(a[2]), "r"(a[3]), "r"(b0), "r"(b1));
}
#define CP_ASYNC16(dst, src) \
    asm volatile("cp.async.cg.shared.global [%0], [%1], 16;" :: "r"(dst), "l"(src))
#define CP_ASYNC16_Z(dst, src, zb) \
    asm volatile("cp.async.cg.shared.global [%0], [%1], 16, %2;" :: "r"(dst), "l"(src), "r"(zb))
#define CP_COMMIT() asm volatile("cp.async.commit_group;" ::: "memory")
#define CP_WAIT1()  asm volatile("cp.async.wait_group 1;" ::: "memory")
#define CP_WAIT0()  asm volatile("cp.async.wait_group 0;" ::: "memory")

// ---------------- setup kernels ----------------
// merged: detect dtype + zero counts (one launch, one block)
__global__ void setup_kernel(const int* __restrict__ dom32) {
    if (threadIdx.x < NEXP) g_counts[threadIdx.x] = 0;
    if (threadIdx.x == 0) {
        int odd_zero = 1;
        for (int i = 1; i < 512; i += 2)
            if (dom32[i] != 0) { odd_zero = 0; break; }
        g_is64 = odd_zero;
    }
}

__global__ void bucket_kernel(const void* __restrict__ dom) {
    int n = blockIdx.x * blockDim.x + threadIdx.x;
    if (n >= N_TOK) return;
    int e = g_is64 ? (int)((const long long*)dom)[n] : ((const int*)dom)[n];
    int p = atomicAdd(&g_counts[e], 1);
    g_idx[e * N_TOK + p] = n;
}

// fused fp32 -> fp16 for x, W1, W2; 2 independent float4 per iteration (MLP=2)
#define NX4  ((N_TOK * DIM) / 4)
#define NW14 ((NEXP * MID * DIM) / 4)
#define NW24 ((NEXP * DIM * MID) / 4)
#define NTOT4 (NX4 + NW14 + NW24)
__device__ __forceinline__ void cvt_one(const float4* __restrict__ s4,
                                        uint2* __restrict__ d2, int j) {
    float4 v = s4[j];
    __half2 a(__float2half_rn(v.x), __float2half_rn(v.y));
    __half2 b(__float2half_rn(v.z), __float2half_rn(v.w));
    d2[j] = make_uint2(*reinterpret_cast<uint32_t*>(&a),
                       *reinterpret_cast<uint32_t*>(&b));
}
__global__ void cvt_all_kernel(const float* __restrict__ x,
                               const float* __restrict__ w1,
                               const float* __restrict__ w2,
                               __half* __restrict__ xd,
                               __half* __restrict__ w1d,
                               __half* __restrict__ w2d) {
    const int tidg = blockIdx.x * blockDim.x + threadIdx.x;
    const int stride = gridDim.x * blockDim.x;
    auto resolve = [&](int i, const float4*& s4, uint2*& d2, int& j) {
        if (i < NX4)              { s4 = (const float4*)x;  d2 = (uint2*)xd;  j = i; }
        else if (i < NX4 + NW14)  { s4 = (const float4*)w1; d2 = (uint2*)w1d; j = i - NX4; }
        else                      { s4 = (const float4*)w2; d2 = (uint2*)w2d; j = i - NX4 - NW14; }
    };
    int i = tidg;
    for (; i + stride < NTOT4; i += 2 * stride) {
        const float4 *sa, *sb; uint2 *da, *db; int ja, jb2;
        resolve(i, sa, da, ja);
        resolve(i + stride, sb, db, jb2);
        float4 va = sa[ja];
        float4 vb = sb[jb2];
        __half2 a0(__float2half_rn(va.x), __float2half_rn(va.y));
        __half2 a1(__float2half_rn(va.z), __float2half_rn(va.w));
        __half2 b0(__float2half_rn(vb.x), __float2half_rn(vb.y));
        __half2 b1(__float2half_rn(vb.z), __float2half_rn(vb.w));
        da[ja]  = make_uint2(*reinterpret_cast<uint32_t*>(&a0), *reinterpret_cast<uint32_t*>(&a1));
        db[jb2] = make_uint2(*reinterpret_cast<uint32_t*>(&b0), *reinterpret_cast<uint32_t*>(&b1));
    }
    if (i < NTOT4) {
        const float4* s4; uint2* d2; int j;
        resolve(i, s4, d2, j);
        cvt_one(s4, d2, j);
    }
}

// ---------------- grouped GEMM: 3-stage cp.async + single-term fp16 mma ----------------
// BM=128 x BN=128; 8 warps 4(m) x 2(n); warp tile 32x64. K chunks of 64 (128 B rows).
// Loop ordering (R10-proven): CP_WAIT1 -> __syncthreads -> issue(kc+2) -> compute(kc).
// The barrier AFTER the wait is what makes other threads' cp.async writes visible.
template <int KDIM, bool IS_G1>
__global__ __launch_bounds__(256, 2)
void moe_gemm_kernel(const float* __restrict__ x,
                     const __half* __restrict__ A_h,
                     const __half* __restrict__ B_h,
                     const float* __restrict__ bias,
                     float* __restrict__ out) {
    constexpr int NCH   = KDIM / KC;
    constexpr int NCOLS = IS_G1 ? MID : DIM;

    const int tiles_per_e = N_TOK / BM;            // 64
    const int e     = blockIdx.x / tiles_per_e;
    const int mtile = blockIdx.x % tiles_per_e;
    const int ntile = blockIdx.y;

    const int cnt  = g_counts[e];
    const int row0 = mtile * BM;
    if (row0 >= cnt) return;
    const int* __restrict__ idx = g_idx + e * N_TOK;

    extern __shared__ char smem[];
    const uint32_t sbase = smem_u32(smem);

    const int tid = threadIdx.x;
    const int wid = tid >> 5;
    const int lid = tid & 31;
    const int mrow0 = (wid & 3) * 32;
    const int ncol0 = (wid >> 2) * 64;

    // ---- cp.async fill mapping: 128 B rows = 8 x 16 B chunks; 256 threads.
    const int c8 = tid & 7;
    const __half* ahp[4];
    const __half* bpp[4];
    uint32_t zbA[4];
    uint32_t sts[4];
#pragma unroll
    for (int i = 0; i < 4; i++) {
        const int row = (tid >> 3) + 32 * i;
        const int grow = row0 + row;
        const bool live = (grow < cnt);
        ahp[i] = live ? A_h + (size_t)idx[grow] * KDIM + c8 * 8 : A_h;
        zbA[i] = live ? 16u : 0u;
        bpp[i] = B_h + ((size_t)e * NCOLS + (size_t)ntile * BN + row) * KDIM + c8 * 8;
        sts[i] = (uint32_t)(row * 128 + ((c8 ^ (row & 7)) << 4));
    }

    auto issue = [&](int ch, int slot) {
        const int k0 = ch * KC;
        const uint32_t st = sbase + (uint32_t)(slot * STAGE_B);
#pragma unroll
        for (int i = 0; i < 4; i++) {
            CP_ASYNC16_Z(st + OFF_A + sts[i], ahp[i] + k0, zbA[i]);
            CP_ASYNC16(st + OFF_B + sts[i], bpp[i] + k0);
        }
        CP_COMMIT();
    };

    float acc[2][8][4];
#pragma unroll
    for (int mi = 0; mi < 2; mi++)
#pragma unroll
        for (int nj = 0; nj < 8; nj++)
#pragma unroll
            for (int q = 0; q < 4; q++) acc[mi][nj][q] = 0.f;

    // ---- ldmatrix per-lane addresses (128 B rows, mask = row&7) ----
    uint32_t aRow[2], aMsk[2];
#pragma unroll
    for (int mi = 0; mi < 2; mi++) {
        const int r = mrow0 + mi * 16 + (lid & 15);
        aRow[mi] = (uint32_t)(r * 128);
        aMsk[mi] = (uint32_t)(r & 7);
    }
    const uint32_t ja = (uint32_t)(lid >> 4);
    uint32_t bRow[4], bMsk[4];
#pragma unroll
    for (int h2 = 0; h2 < 4; h2++) {
        const int r = ncol0 + h2 * 16 + (lid & 7) + 8 * (lid >> 4);
        bRow[h2] = (uint32_t)(r * 128);
        bMsk[h2] = (uint32_t)(r & 7);
    }
    const uint32_t jb = (uint32_t)((lid >> 3) & 1);

    issue(0, 0);
    issue(1, 1);

    int slot = 0;                       // slot of chunk kc
    for (int kc = 0; kc < NCH; kc++) {
        CP_WAIT1();                     // chunk kc has landed (this thread's groups)
        __syncthreads();                // all threads' waits done -> tile fully visible;
                                        // also: all warps done computing kc-1 -> slot reusable
        if (kc + 2 < NCH) {
            int s2 = slot + 2;
            if (s2 >= NSTAGE) s2 -= NSTAGE;
            issue(kc + 2, s2);
        } else {
            CP_COMMIT();                // uniform group accounting
        }

        const uint32_t sa = sbase + (uint32_t)(slot * STAGE_B);
#pragma unroll
        for (int ks = 0; ks < 4; ks++) {
            uint32_t ah[2][4], bf[4][4];
#pragma unroll
            for (int mi = 0; mi < 2; mi++) {
                const uint32_t adr = sa + aRow[mi] + ((((uint32_t)(2 * ks) + ja) ^ aMsk[mi]) << 4);
                ldm_x4(ah[mi], adr + OFF_A);
            }
#pragma unroll
            for (int h2 = 0; h2 < 4; h2++) {
                const uint32_t adr = sa + bRow[h2] + ((((uint32_t)(2 * ks) + jb) ^ bMsk[h2]) << 4);
                ldm_x4(bf[h2], adr + OFF_B);
            }
#pragma unroll
            for (int mi = 0; mi < 2; mi++)
#pragma unroll
                for (int nj = 0; nj < 8; nj++) {
                    const int h2 = nj >> 1, sl = nj & 1;
                    mma16816h(acc[mi][nj], ah[mi], bf[h2][2 * sl], bf[h2][2 * sl + 1]);
                }
        }
        if (++slot == NSTAGE) slot = 0;
    }
    CP_WAIT0();

    // ---- epilogue ----
    const int lr = lid >> 2;
    const int c2 = (lid & 3) * 2;
    const float* __restrict__ bb = bias + (size_t)e * NCOLS + (size_t)ntile * BN;

#pragma unroll
    for (int mi = 0; mi < 2; mi++) {
#pragma unroll
        for (int half = 0; half < 2; half++) {
            const int rloc = mrow0 + mi * 16 + lr + half * 8;
            const int grow = row0 + rloc;
            if (grow < cnt) {
                const long long tok = idx[grow];
#pragma unroll
                for (int nj = 0; nj < 8; nj++) {
                    const int col = ncol0 + nj * 8 + c2;
                    const float v0 = acc[mi][nj][half * 2 + 0];
                    const float v1 = acc[mi][nj][half * 2 + 1];
                    if (IS_G1) {
                        float r0 = v0 + bb[col];
                        float r1 = v1 + bb[col + 1];
                        r0 = r0 > 0.f ? r0 : 0.f;
                        r1 = r1 > 0.f ? r1 : 0.f;
                        __half2 hv(__float2half_rn(r0), __float2half_rn(r1));
                        *(uint32_t*)(g_h + (size_t)tok * MID + (size_t)ntile * BN + col) =
                            *reinterpret_cast<uint32_t*>(&hv);
                    } else {
                        const size_t o = (size_t)tok * DIM + (size_t)ntile * BN + col;
                        float2 xv = *(const float2*)(x + o);
                        *(float2*)(out + o) =
                            make_float2(xv.x + v0 + bb[col], xv.y + v1 + bb[col + 1]);
                    }
                }
            }
        }
    }
}

// ---------------- host launch ----------------
extern "C" void kernel_launch(void* const* d_in, const int* in_sizes, int n_in,
                              void* d_out, int out_size) {
    const float* x       = (const float*)d_in[0];
    const void*  domains = d_in[1];
    const float* W1      = (const float*)d_in[2];
    const float* b1      = (const float*)d_in[3];
    const float* W2      = (const float*)d_in[4];
    const float* b2      = (const float*)d_in[5];
    float*       out     = (float*)d_out;

    setup_kernel<<<1, 32>>>((const int*)domains);
    bucket_kernel<<<(N_TOK + 255) / 256, 256>>>(domains);

    __half *xh, *w1h, *w2h, *hh;
    cudaGetSymbolAddress((void**)&xh,  g_x);
    cudaGetSymbolAddress((void**)&w1h, g_w1);
    cudaGetSymbolAddress((void**)&w2h, g_w2);
    cudaGetSymbolAddress((void**)&hh,  g_h);

    cvt_all_kernel<<<2048, 256>>>(x, W1, W2, xh, w1h, w2h);

    cudaFuncSetAttribute(moe_gemm_kernel<DIM, true>,
                         cudaFuncAttributeMaxDynamicSharedMemorySize, SMEM_TOT);
    cudaFuncSetAttribute(moe_gemm_kernel<MID, false>,
                         cudaFuncAttributeMaxDynamicSharedMemorySize, SMEM_TOT);

    dim3 grid1(NEXP * (N_TOK / BM), MID / BN);   // (256, 4)
    moe_gemm_kernel<DIM, true><<<grid1, 256, SMEM_TOT>>>(x, xh, w1h, b1, nullptr);

    dim3 grid2(NEXP * (N_TOK / BM), DIM / BN);   // (256, 16)
    moe_gemm_kernel<MID, false><<<grid2, 256, SMEM_TOT>>>(x, hh, w2h, b2, out);
}